// round 1
// baseline (speedup 1.0000x reference)
#include <cuda_runtime.h>
#include <math.h>

#define N_TOK 8192
#define DM    1024
#define DFF   4096
#define NE    8
#define TOPK  2
#define CAP   1280

// ---------------- scratch (global device memory, no allocations) ----------------
__device__ float g_buf[2 * NE * CAP * DM];           //  84 MB  dispatched tokens
__device__ float g_h  [2 * NE * CAP * DFF];          // 336 MB  hidden (silu(w1x)*w3x)
__device__ float g_ob [2 * NE * CAP * DM];           //  84 MB  expert outputs
__device__ float g_probs[N_TOK * NE];                // router probs (for aux)
__device__ int   g_top_idx[N_TOK * TOPK];
__device__ float g_top_w [N_TOK * TOPK];
__device__ int   g_pos   [N_TOK * TOPK];
__device__ int   g_cnt   [TOPK * NE];                // pre-capacity counts per (k,e)

// ---------------- 1. router: logits, softmax, top-2, weights ----------------
__global__ __launch_bounds__(256) void router_kernel(const float* __restrict__ x,
                                                     const float* __restrict__ gw) {
    int warp = (blockIdx.x * blockDim.x + threadIdx.x) >> 5;
    int lane = threadIdx.x & 31;
    if (warp >= N_TOK) return;
    const float* xr = x + (size_t)warp * DM;
    float acc[NE];
#pragma unroll
    for (int e = 0; e < NE; e++) acc[e] = 0.f;
    for (int i = lane; i < DM; i += 32) {
        float xv = xr[i];
#pragma unroll
        for (int e = 0; e < NE; e++) acc[e] += xv * gw[e * DM + i];
    }
#pragma unroll
    for (int off = 16; off > 0; off >>= 1)
#pragma unroll
        for (int e = 0; e < NE; e++) acc[e] += __shfl_xor_sync(0xffffffffu, acc[e], off);

    if (lane == 0) {
        float mx = acc[0];
#pragma unroll
        for (int e = 1; e < NE; e++) mx = fmaxf(mx, acc[e]);
        float p[NE], s = 0.f;
#pragma unroll
        for (int e = 0; e < NE; e++) { p[e] = expf(acc[e] - mx); s += p[e]; }
        float inv = 1.f / s;
        int i0 = 0;
#pragma unroll
        for (int e = 1; e < NE; e++) if (p[e] > p[i0]) i0 = e;
        int i1 = (i0 == 0) ? 1 : 0;
#pragma unroll
        for (int e = 0; e < NE; e++) if (e != i0 && e != i1 && p[e] > p[i1]) i1 = e;
#pragma unroll
        for (int e = 0; e < NE; e++) g_probs[warp * NE + e] = p[e] * inv;
        float p0 = p[i0] * inv, p1 = p[i1] * inv;
        float ws = p0 + p1 + 1e-10f;
        g_top_idx[warp * 2 + 0] = i0;  g_top_w[warp * 2 + 0] = p0 / ws;
        g_top_idx[warp * 2 + 1] = i1;  g_top_w[warp * 2 + 1] = p1 / ws;
    }
}

// ---------------- 2. capacity scan: exact token-order cumsum positions ----------------
__global__ __launch_bounds__(256) void scan_kernel() {
    int k = blockIdx.x;                 // 0..1
    int t = threadIdx.x;                // 256 threads
    const int CH = N_TOK / 256;         // 32 tokens per thread
    __shared__ int cnt[256][NE];
    int local[NE];
#pragma unroll
    for (int e = 0; e < NE; e++) local[e] = 0;
    for (int i = 0; i < CH; i++) {
        int e = g_top_idx[(t * CH + i) * 2 + k];
        local[e]++;
    }
#pragma unroll
    for (int e = 0; e < NE; e++) cnt[t][e] = local[e];
    __syncthreads();
    if (t < NE) {                       // serial exclusive scan per expert column
        int run = 0;
        for (int i = 0; i < 256; i++) { int v = cnt[i][t]; cnt[i][t] = run; run += v; }
        g_cnt[k * NE + t] = run;        // pre-capacity total
    }
    __syncthreads();
    int off[NE];
#pragma unroll
    for (int e = 0; e < NE; e++) off[e] = cnt[t][e];
    for (int i = 0; i < CH; i++) {
        int tk = (t * CH + i) * 2 + k;
        int e = g_top_idx[tk];
        g_pos[tk] = off[e]++;
    }
}

// ---------------- 3. gather tokens into per-(k,e) buffers ----------------
__global__ __launch_bounds__(256) void gather_kernel(const float* __restrict__ x) {
    int tk = blockIdx.x;                // token*2 + k
    int pos = g_pos[tk];
    if (pos >= CAP) return;
    int e = g_top_idx[tk];
    int k = tk & 1, t = tk >> 1;
    float4*       dst = (float4*)(g_buf + ((size_t)(k * NE + e) * CAP + pos) * DM);
    const float4* src = (const float4*)(x + (size_t)t * DM);
    dst[threadIdx.x] = src[threadIdx.x];      // 256 * float4 = 1024 floats
}

// ---------------- 4. fused GEMM: h = silu(buf@w1^T) * (buf@w3^T) ----------------
// 128x64x16 tiles, 8x4 microtile, 256 threads, w1/w3 share the A tile.
__global__ __launch_bounds__(256) void gemm13_kernel(const float* __restrict__ W1,
                                                     const float* __restrict__ W3) {
    int z = blockIdx.z, e = z & (NE - 1);
    int rows = g_cnt[z]; if (rows > CAP) rows = CAP;
    int m0 = blockIdx.y * 128;
    if (m0 >= rows) return;
    int n0 = blockIdx.x * 64;
    const float* A  = g_buf + (size_t)z * CAP * DM;
    const float* B1 = W1 + (size_t)e * DFF * DM;
    const float* B3 = W3 + (size_t)e * DFF * DM;
    float*       H  = g_h + (size_t)z * CAP * DFF;

    __shared__ float As [16][128];
    __shared__ float Bs1[16][64];
    __shared__ float Bs3[16][64];

    int tid = threadIdx.x, tx = tid & 15, ty = tid >> 4;
    float acc1[8][4], acc2[8][4];
#pragma unroll
    for (int i = 0; i < 8; i++)
#pragma unroll
        for (int j = 0; j < 4; j++) { acc1[i][j] = 0.f; acc2[i][j] = 0.f; }

    for (int k0 = 0; k0 < DM; k0 += 16) {
#pragma unroll
        for (int i = 0; i < 8; i++) {
            int idx = tid + i * 256;
            As[idx & 15][idx >> 4] = A[(size_t)(m0 + (idx >> 4)) * DM + k0 + (idx & 15)];
        }
#pragma unroll
        for (int i = 0; i < 4; i++) {
            int idx = tid + i * 256; int n = idx >> 4, kk = idx & 15;
            Bs1[kk][n] = B1[(size_t)(n0 + n) * DM + k0 + kk];
            Bs3[kk][n] = B3[(size_t)(n0 + n) * DM + k0 + kk];
        }
        __syncthreads();
#pragma unroll
        for (int kk = 0; kk < 16; kk++) {
            float4 a0 = *(const float4*)&As[kk][ty * 8];
            float4 a1 = *(const float4*)&As[kk][ty * 8 + 4];
            float a[8] = {a0.x, a0.y, a0.z, a0.w, a1.x, a1.y, a1.z, a1.w};
            float4 v1 = *(const float4*)&Bs1[kk][tx * 4];
            float4 v3 = *(const float4*)&Bs3[kk][tx * 4];
            float b1[4] = {v1.x, v1.y, v1.z, v1.w};
            float b3[4] = {v3.x, v3.y, v3.z, v3.w};
#pragma unroll
            for (int i = 0; i < 8; i++)
#pragma unroll
                for (int j = 0; j < 4; j++) {
                    acc1[i][j] += a[i] * b1[j];
                    acc2[i][j] += a[i] * b3[j];
                }
        }
        __syncthreads();
    }
#pragma unroll
    for (int i = 0; i < 8; i++) {
        int m = m0 + ty * 8 + i;
        if (m < rows) {
            float4 hv;
            float v;
            v = acc1[i][0]; hv.x = (v / (1.f + expf(-v))) * acc2[i][0];
            v = acc1[i][1]; hv.y = (v / (1.f + expf(-v))) * acc2[i][1];
            v = acc1[i][2]; hv.z = (v / (1.f + expf(-v))) * acc2[i][2];
            v = acc1[i][3]; hv.w = (v / (1.f + expf(-v))) * acc2[i][3];
            *(float4*)&H[(size_t)m * DFF + n0 + tx * 4] = hv;
        }
    }
}

// ---------------- 5. GEMM: ob = h @ w2^T  (M<=1280, N=1024, K=4096) ----------------
__global__ __launch_bounds__(256) void gemm2_kernel(const float* __restrict__ W2) {
    int z = blockIdx.z, e = z & (NE - 1);
    int rows = g_cnt[z]; if (rows > CAP) rows = CAP;
    int m0 = blockIdx.y * 128;
    if (m0 >= rows) return;
    int n0 = blockIdx.x * 64;
    const float* A = g_h + (size_t)z * CAP * DFF;
    const float* B = W2 + (size_t)e * DM * DFF;   // [DM][DFF] row-major, N x K
    float*       O = g_ob + (size_t)z * CAP * DM;

    __shared__ float As[16][128];
    __shared__ float Bs[16][64];

    int tid = threadIdx.x, tx = tid & 15, ty = tid >> 4;
    float acc[8][4];
#pragma unroll
    for (int i = 0; i < 8; i++)
#pragma unroll
        for (int j = 0; j < 4; j++) acc[i][j] = 0.f;

    for (int k0 = 0; k0 < DFF; k0 += 16) {
#pragma unroll
        for (int i = 0; i < 8; i++) {
            int idx = tid + i * 256;
            As[idx & 15][idx >> 4] = A[(size_t)(m0 + (idx >> 4)) * DFF + k0 + (idx & 15)];
        }
#pragma unroll
        for (int i = 0; i < 4; i++) {
            int idx = tid + i * 256; int n = idx >> 4, kk = idx & 15;
            Bs[kk][n] = B[(size_t)(n0 + n) * DFF + k0 + kk];
        }
        __syncthreads();
#pragma unroll
        for (int kk = 0; kk < 16; kk++) {
            float4 a0 = *(const float4*)&As[kk][ty * 8];
            float4 a1 = *(const float4*)&As[kk][ty * 8 + 4];
            float a[8] = {a0.x, a0.y, a0.z, a0.w, a1.x, a1.y, a1.z, a1.w};
            float4 vb = *(const float4*)&Bs[kk][tx * 4];
            float b[4] = {vb.x, vb.y, vb.z, vb.w};
#pragma unroll
            for (int i = 0; i < 8; i++)
#pragma unroll
                for (int j = 0; j < 4; j++) acc[i][j] += a[i] * b[j];
        }
        __syncthreads();
    }
#pragma unroll
    for (int i = 0; i < 8; i++) {
        int m = m0 + ty * 8 + i;
        if (m < rows) {
            float4 ov = {acc[i][0], acc[i][1], acc[i][2], acc[i][3]};
            *(float4*)&O[(size_t)m * DM + n0 + tx * 4] = ov;
        }
    }
}

// ---------------- 6. weighted scatter/combine ----------------
__global__ __launch_bounds__(256) void scatter_kernel(float* __restrict__ out) {
    int t = blockIdx.x;
    int d4 = threadIdx.x;
    float4 acc = {0.f, 0.f, 0.f, 0.f};
#pragma unroll
    for (int k = 0; k < TOPK; k++) {
        int tk = t * 2 + k;
        int pos = g_pos[tk];
        if (pos < CAP) {
            int e = g_top_idx[tk];
            float w = g_top_w[tk];
            float4 v = ((const float4*)(g_ob + ((size_t)(k * NE + e) * CAP + pos) * DM))[d4];
            acc.x += v.x * w; acc.y += v.y * w; acc.z += v.z * w; acc.w += v.w * w;
        }
    }
    ((float4*)(out + (size_t)t * DM))[d4] = acc;
}

// ---------------- 7. aux loss (deterministic fixed-order reduction) ----------------
__global__ __launch_bounds__(256) void aux_kernel(float* __restrict__ out, int out_size) {
    __shared__ float red[256];
    __shared__ float Ps[NE];
    int tid = threadIdx.x;
    float loc[NE];
#pragma unroll
    for (int e = 0; e < NE; e++) loc[e] = 0.f;
    for (int i = tid; i < N_TOK; i += 256) {
#pragma unroll
        for (int e = 0; e < NE; e++) loc[e] += g_probs[i * NE + e];
    }
    for (int e = 0; e < NE; e++) {
        red[tid] = loc[e];
        __syncthreads();
        for (int s = 128; s > 0; s >>= 1) {
            if (tid < s) red[tid] += red[tid + s];
            __syncthreads();
        }
        if (tid == 0) Ps[e] = red[0];
        __syncthreads();
    }
    if (tid == 0) {
        float aux = 0.f;
        for (int e = 0; e < NE; e++) {
            float f = (float)(g_cnt[e] + g_cnt[NE + e]) / (float)(N_TOK * TOPK);
            float P = Ps[e] / (float)N_TOK;
            aux += f * P;
        }
        out[out_size - 1] = aux * (float)NE;
    }
}

// ---------------- launch ----------------
extern "C" void kernel_launch(void* const* d_in, const int* in_sizes, int n_in,
                              void* d_out, int out_size) {
    const float* x    = (const float*)d_in[0];
    const float* gw   = (const float*)d_in[1];
    const float* w1   = (const float*)d_in[2];
    const float* w2   = (const float*)d_in[3];
    const float* w3   = (const float*)d_in[4];
    float* out = (float*)d_out;

    router_kernel<<<N_TOK / 8, 256>>>(x, gw);
    scan_kernel<<<2, 256>>>();
    gather_kernel<<<N_TOK * TOPK, 256>>>(x);

    dim3 g1(DFF / 64, CAP / 128, TOPK * NE);   // 64 x 10 x 16
    gemm13_kernel<<<g1, 256>>>(w1, w3);

    dim3 g2(DM / 64, CAP / 128, TOPK * NE);    // 16 x 10 x 16
    gemm2_kernel<<<g2, 256>>>(w2);

    scatter_kernel<<<N_TOK, 256>>>(out);
    aux_kernel<<<1, 256>>>(out, out_size);
}

// round 3
// speedup vs baseline: 5.7307x; 5.7307x over previous
#include <cuda_runtime.h>
#include <math.h>
#include <stdint.h>

#define N_TOK 8192
#define DM    1024
#define DFF   4096
#define NE    8
#define TOPK  2
#define CAP   1280
#define PAD   36        // smem row stride in floats (32 data + 4 pad)

// ---------------- scratch ----------------
__device__ float g_buf[2 * NE * CAP * DM];
__device__ float g_h  [2 * NE * CAP * DFF];
__device__ float g_ob [2 * NE * CAP * DM];
__device__ float g_probs[N_TOK * NE];
__device__ int   g_top_idx[N_TOK * TOPK];
__device__ float g_top_w [N_TOK * TOPK];
__device__ int   g_pos   [N_TOK * TOPK];
__device__ int   g_cnt   [TOPK * NE];

// ---------------- helpers ----------------
__device__ __forceinline__ uint32_t tf32r(float x) {
    uint32_t r; asm("cvt.rna.tf32.f32 %0, %1;" : "=r"(r) : "f"(x)); return r;
}
__device__ __forceinline__ void mma_tf32(float* c, const uint32_t* a, uint32_t b0, uint32_t b1) {
    asm volatile(
        "mma.sync.aligned.m16n8k8.row.col.f32.tf32.tf32.f32 "
        "{%0,%1,%2,%3}, {%4,%5,%6,%7}, {%8,%9}, {%0,%1,%2,%3};"
        : "+f"(c[0]), "+f"(c[1]), "+f"(c[2]), "+f"(c[3])
        : "r"(a[0]), "r"(a[1]), "r"(a[2]), "r"(a[3]), "r"(b0), "r"(b1));
}
// fill rows x 32 tf32 tile into padded smem; rows*8 float4s, 256 threads
template<int ROWS>
__device__ __forceinline__ void fill32(float* s, const float* __restrict__ g,
                                       int stride, int tid) {
#pragma unroll
    for (int i = 0; i < ROWS * 8 / 256; i++) {
        int f = tid + i * 256;
        int r = f >> 3, c4 = f & 7;
        float4 v = *(const float4*)(g + (size_t)r * stride + c4 * 4);
        uint32_t* d = (uint32_t*)(s + r * PAD + c4 * 4);
        d[0] = tf32r(v.x); d[1] = tf32r(v.y); d[2] = tf32r(v.z); d[3] = tf32r(v.w);
    }
}

// ---------------- 1. router ----------------
__global__ __launch_bounds__(256) void router_kernel(const float* __restrict__ x,
                                                     const float* __restrict__ gw) {
    int warp = (blockIdx.x * blockDim.x + threadIdx.x) >> 5;
    int lane = threadIdx.x & 31;
    if (warp >= N_TOK) return;
    const float* xr = x + (size_t)warp * DM;
    float acc[NE];
#pragma unroll
    for (int e = 0; e < NE; e++) acc[e] = 0.f;
    for (int i = lane; i < DM; i += 32) {
        float xv = xr[i];
#pragma unroll
        for (int e = 0; e < NE; e++) acc[e] += xv * gw[e * DM + i];
    }
#pragma unroll
    for (int off = 16; off > 0; off >>= 1)
#pragma unroll
        for (int e = 0; e < NE; e++) acc[e] += __shfl_xor_sync(0xffffffffu, acc[e], off);
    if (lane == 0) {
        float mx = acc[0];
#pragma unroll
        for (int e = 1; e < NE; e++) mx = fmaxf(mx, acc[e]);
        float p[NE], s = 0.f;
#pragma unroll
        for (int e = 0; e < NE; e++) { p[e] = expf(acc[e] - mx); s += p[e]; }
        float inv = 1.f / s;
        int i0 = 0;
#pragma unroll
        for (int e = 1; e < NE; e++) if (p[e] > p[i0]) i0 = e;
        int i1 = (i0 == 0) ? 1 : 0;
#pragma unroll
        for (int e = 0; e < NE; e++) if (e != i0 && e != i1 && p[e] > p[i1]) i1 = e;
#pragma unroll
        for (int e = 0; e < NE; e++) g_probs[warp * NE + e] = p[e] * inv;
        float p0 = p[i0] * inv, p1 = p[i1] * inv;
        float ws = p0 + p1 + 1e-10f;
        g_top_idx[warp * 2 + 0] = i0;  g_top_w[warp * 2 + 0] = p0 / ws;
        g_top_idx[warp * 2 + 1] = i1;  g_top_w[warp * 2 + 1] = p1 / ws;
    }
}

// ---------------- 2. capacity scan ----------------
__global__ __launch_bounds__(256) void scan_kernel() {
    int k = blockIdx.x;
    int t = threadIdx.x;
    const int CH = N_TOK / 256;
    __shared__ int cnt[256][NE];
    int local[NE];
#pragma unroll
    for (int e = 0; e < NE; e++) local[e] = 0;
    for (int i = 0; i < CH; i++) local[g_top_idx[(t * CH + i) * 2 + k]]++;
#pragma unroll
    for (int e = 0; e < NE; e++) cnt[t][e] = local[e];
    __syncthreads();
    if (t < NE) {
        int run = 0;
        for (int i = 0; i < 256; i++) { int v = cnt[i][t]; cnt[i][t] = run; run += v; }
        g_cnt[k * NE + t] = run;
    }
    __syncthreads();
    int off[NE];
#pragma unroll
    for (int e = 0; e < NE; e++) off[e] = cnt[t][e];
    for (int i = 0; i < CH; i++) {
        int tk = (t * CH + i) * 2 + k;
        g_pos[tk] = off[g_top_idx[tk]]++;
    }
}

// ---------------- 3. gather ----------------
__global__ __launch_bounds__(256) void gather_kernel(const float* __restrict__ x) {
    int tk = blockIdx.x;
    int pos = g_pos[tk];
    if (pos >= CAP) return;
    int e = g_top_idx[tk];
    int k = tk & 1, t = tk >> 1;
    float4*       dst = (float4*)(g_buf + ((size_t)(k * NE + e) * CAP + pos) * DM);
    const float4* src = (const float4*)(x + (size_t)t * DM);
    dst[threadIdx.x] = src[threadIdx.x];
}

// ---------------- 4. gemm13 (tf32 mma.sync): h = silu(A@W1^T) * (A@W3^T) ----------------
// block 128M x 64N, K-chunk 32, 8 warps in 4x2, warp tile 32x32 (per matrix)
__global__ __launch_bounds__(256, 2) void gemm13_mma(const float* __restrict__ W1,
                                                     const float* __restrict__ W3) {
    int z = blockIdx.z, e = z & (NE - 1);
    int rows = g_cnt[z]; if (rows > CAP) rows = CAP;
    int m0 = blockIdx.y * 128; if (m0 >= rows) return;
    int n0 = blockIdx.x * 64;

    __shared__ float As [128 * PAD];
    __shared__ float B1s[ 64 * PAD];
    __shared__ float B3s[ 64 * PAD];

    const float* gA  = g_buf + (size_t)z * CAP * DM + (size_t)m0 * DM;
    const float* gB1 = W1 + (size_t)e * DFF * DM + (size_t)n0 * DM;
    const float* gB3 = W3 + (size_t)e * DFF * DM + (size_t)n0 * DM;

    int tid = threadIdx.x, wid = tid >> 5, lane = tid & 31;
    int wm = wid >> 1, wn = wid & 1;          // warp row/col
    int g = lane >> 2, tg = lane & 3;

    float acc1[2][4][4], acc2[2][4][4];
#pragma unroll
    for (int mi = 0; mi < 2; mi++)
#pragma unroll
        for (int ni = 0; ni < 4; ni++)
#pragma unroll
            for (int r = 0; r < 4; r++) { acc1[mi][ni][r] = 0.f; acc2[mi][ni][r] = 0.f; }

    for (int c = 0; c < DM / 32; c++) {
        int k0 = c * 32;
        fill32<128>(As,  gA  + k0, DM, tid);
        fill32< 64>(B1s, gB1 + k0, DM, tid);
        fill32< 64>(B3s, gB3 + k0, DM, tid);
        __syncthreads();
#pragma unroll
        for (int kk = 0; kk < 4; kk++) {
            int k = kk * 8;
            uint32_t a[2][4];
#pragma unroll
            for (int mi = 0; mi < 2; mi++) {
                int mb = wm * 32 + mi * 16;
                a[mi][0] = __float_as_uint(As[(mb + g) * PAD + k + tg]);
                a[mi][1] = __float_as_uint(As[(mb + 8 + g) * PAD + k + tg]);
                a[mi][2] = __float_as_uint(As[(mb + g) * PAD + k + 4 + tg]);
                a[mi][3] = __float_as_uint(As[(mb + 8 + g) * PAD + k + 4 + tg]);
            }
#pragma unroll
            for (int ni = 0; ni < 4; ni++) {
                int nb = wn * 32 + ni * 8;
                uint32_t b0 = __float_as_uint(B1s[(nb + g) * PAD + k + tg]);
                uint32_t b1 = __float_as_uint(B1s[(nb + g) * PAD + k + 4 + tg]);
                mma_tf32(acc1[0][ni], a[0], b0, b1);
                mma_tf32(acc1[1][ni], a[1], b0, b1);
                uint32_t d0 = __float_as_uint(B3s[(nb + g) * PAD + k + tg]);
                uint32_t d1 = __float_as_uint(B3s[(nb + g) * PAD + k + 4 + tg]);
                mma_tf32(acc2[0][ni], a[0], d0, d1);
                mma_tf32(acc2[1][ni], a[1], d0, d1);
            }
        }
        __syncthreads();
    }

    float* H = g_h + (size_t)z * CAP * DFF;
#pragma unroll
    for (int mi = 0; mi < 2; mi++)
#pragma unroll
        for (int half = 0; half < 2; half++) {
            int m = m0 + wm * 32 + mi * 16 + half * 8 + g;
            if (m < rows) {
#pragma unroll
                for (int ni = 0; ni < 4; ni++) {
                    float v0 = acc1[mi][ni][half * 2 + 0];
                    float v1 = acc1[mi][ni][half * 2 + 1];
                    float o0 = (v0 / (1.f + expf(-v0))) * acc2[mi][ni][half * 2 + 0];
                    float o1 = (v1 / (1.f + expf(-v1))) * acc2[mi][ni][half * 2 + 1];
                    int col = n0 + wn * 32 + ni * 8 + 2 * tg;
                    *(float2*)&H[(size_t)m * DFF + col] = make_float2(o0, o1);
                }
            }
        }
}

// ---------------- 5. gemm2 (tf32 mma.sync): ob = h @ w2^T ----------------
// block 128M x 128N, K-chunk 32, 8 warps in 4x2, warp tile 32x64
__global__ __launch_bounds__(256, 2) void gemm2_mma(const float* __restrict__ W2) {
    int z = blockIdx.z, e = z & (NE - 1);
    int rows = g_cnt[z]; if (rows > CAP) rows = CAP;
    int m0 = blockIdx.y * 128; if (m0 >= rows) return;
    int n0 = blockIdx.x * 128;

    __shared__ float As[128 * PAD];
    __shared__ float Bs[128 * PAD];

    const float* gA = g_h + (size_t)z * CAP * DFF + (size_t)m0 * DFF;
    const float* gB = W2 + (size_t)e * DM * DFF + (size_t)n0 * DFF;

    int tid = threadIdx.x, wid = tid >> 5, lane = tid & 31;
    int wm = wid >> 1, wn = wid & 1;
    int g = lane >> 2, tg = lane & 3;

    float acc[2][8][4];
#pragma unroll
    for (int mi = 0; mi < 2; mi++)
#pragma unroll
        for (int ni = 0; ni < 8; ni++)
#pragma unroll
            for (int r = 0; r < 4; r++) acc[mi][ni][r] = 0.f;

    for (int c = 0; c < DFF / 32; c++) {
        int k0 = c * 32;
        fill32<128>(As, gA + k0, DFF, tid);
        fill32<128>(Bs, gB + k0, DFF, tid);
        __syncthreads();
#pragma unroll
        for (int kk = 0; kk < 4; kk++) {
            int k = kk * 8;
            uint32_t a[2][4];
#pragma unroll
            for (int mi = 0; mi < 2; mi++) {
                int mb = wm * 32 + mi * 16;
                a[mi][0] = __float_as_uint(As[(mb + g) * PAD + k + tg]);
                a[mi][1] = __float_as_uint(As[(mb + 8 + g) * PAD + k + tg]);
                a[mi][2] = __float_as_uint(As[(mb + g) * PAD + k + 4 + tg]);
                a[mi][3] = __float_as_uint(As[(mb + 8 + g) * PAD + k + 4 + tg]);
            }
#pragma unroll
            for (int ni = 0; ni < 8; ni++) {
                int nb = wn * 64 + ni * 8;
                uint32_t b0 = __float_as_uint(Bs[(nb + g) * PAD + k + tg]);
                uint32_t b1 = __float_as_uint(Bs[(nb + g) * PAD + k + 4 + tg]);
                mma_tf32(acc[0][ni], a[0], b0, b1);
                mma_tf32(acc[1][ni], a[1], b0, b1);
            }
        }
        __syncthreads();
    }

    float* O = g_ob + (size_t)z * CAP * DM;
#pragma unroll
    for (int mi = 0; mi < 2; mi++)
#pragma unroll
        for (int half = 0; half < 2; half++) {
            int m = m0 + wm * 32 + mi * 16 + half * 8 + g;
            if (m < rows) {
#pragma unroll
                for (int ni = 0; ni < 8; ni++) {
                    int col = n0 + wn * 64 + ni * 8 + 2 * tg;
                    *(float2*)&O[(size_t)m * DM + col] =
                        make_float2(acc[mi][ni][half * 2 + 0], acc[mi][ni][half * 2 + 1]);
                }
            }
        }
}

// ---------------- 6. weighted scatter/combine ----------------
__global__ __launch_bounds__(256) void scatter_kernel(float* __restrict__ out) {
    int t = blockIdx.x;
    int d4 = threadIdx.x;
    float4 acc = {0.f, 0.f, 0.f, 0.f};
#pragma unroll
    for (int k = 0; k < TOPK; k++) {
        int tk = t * 2 + k;
        int pos = g_pos[tk];
        if (pos < CAP) {
            int e = g_top_idx[tk];
            float w = g_top_w[tk];
            float4 v = ((const float4*)(g_ob + ((size_t)(k * NE + e) * CAP + pos) * DM))[d4];
            acc.x += v.x * w; acc.y += v.y * w; acc.z += v.z * w; acc.w += v.w * w;
        }
    }
    ((float4*)(out + (size_t)t * DM))[d4] = acc;
}

// ---------------- 7. aux loss ----------------
__global__ __launch_bounds__(256) void aux_kernel(float* __restrict__ out, int out_size) {
    __shared__ float red[256];
    __shared__ float Ps[NE];
    int tid = threadIdx.x;
    float loc[NE];
#pragma unroll
    for (int e = 0; e < NE; e++) loc[e] = 0.f;
    for (int i = tid; i < N_TOK; i += 256) {
#pragma unroll
        for (int e = 0; e < NE; e++) loc[e] += g_probs[i * NE + e];
    }
    for (int e = 0; e < NE; e++) {
        red[tid] = loc[e];
        __syncthreads();
        for (int s = 128; s > 0; s >>= 1) {
            if (tid < s) red[tid] += red[tid + s];
            __syncthreads();
        }
        if (tid == 0) Ps[e] = red[0];
        __syncthreads();
    }
    if (tid == 0) {
        float aux = 0.f;
        for (int e = 0; e < NE; e++) {
            float f = (float)(g_cnt[e] + g_cnt[NE + e]) / (float)(N_TOK * TOPK);
            float P = Ps[e] / (float)N_TOK;
            aux += f * P;
        }
        out[out_size - 1] = aux * (float)NE;
    }
}

// ---------------- launch ----------------
extern "C" void kernel_launch(void* const* d_in, const int* in_sizes, int n_in,
                              void* d_out, int out_size) {
    const float* x  = (const float*)d_in[0];
    const float* gw = (const float*)d_in[1];
    const float* w1 = (const float*)d_in[2];
    const float* w2 = (const float*)d_in[3];
    const float* w3 = (const float*)d_in[4];
    float* out = (float*)d_out;

    router_kernel<<<N_TOK / 8, 256>>>(x, gw);
    scan_kernel<<<2, 256>>>();
    gather_kernel<<<N_TOK * TOPK, 256>>>(x);

    dim3 g1(DFF / 64, CAP / 128, TOPK * NE);    // 64 x 10 x 16
    gemm13_mma<<<g1, 256>>>(w1, w3);

    dim3 g2(DM / 128, CAP / 128, TOPK * NE);    // 8 x 10 x 16
    gemm2_mma<<<g2, 256>>>(w2);

    scatter_kernel<<<N_TOK, 256>>>(out);
    aux_kernel<<<1, 256>>>(out, out_size);
}

// round 4
// speedup vs baseline: 5.8904x; 1.0279x over previous
#include <cuda_runtime.h>
#include <math.h>
#include <stdint.h>

#define N_TOK 8192
#define DM    1024
#define DFF   4096
#define NE    8
#define TOPK  2
#define CAP   1280
#define PAD   36          // smem row stride in floats
#define SROWB 144         // row stride bytes
#define SSTAGE 55296      // bytes per pipeline stage (A + B tiles)

// ---------------- scratch ----------------
__device__ float g_buf[2 * NE * CAP * DM];
__device__ float g_h  [2 * NE * CAP * DFF];
__device__ float g_ob [2 * NE * CAP * DM];
__device__ float g_w1t[NE * DFF * DM];
__device__ float g_w3t[NE * DFF * DM];
__device__ float g_w2t[NE * DM * DFF];
__device__ float g_probs[N_TOK * NE];
__device__ int   g_top_idx[N_TOK * TOPK];
__device__ float g_top_w [N_TOK * TOPK];
__device__ int   g_pos   [N_TOK * TOPK];
__device__ int   g_cnt   [TOPK * NE];

// ---------------- helpers ----------------
__device__ __forceinline__ uint32_t smem_u32(const void* p) {
    uint32_t a;
    asm("{ .reg .u64 t; cvta.to.shared.u64 t, %1; cvt.u32.u64 %0, t; }" : "=r"(a) : "l"(p));
    return a;
}
__device__ __forceinline__ float tf32f(float x) {
    uint32_t r; asm("cvt.rna.tf32.f32 %0, %1;" : "=r"(r) : "f"(x));
    return __uint_as_float(r);
}
__device__ __forceinline__ void mma_tf32(float* c, const uint32_t* a, uint32_t b0, uint32_t b1) {
    asm volatile(
        "mma.sync.aligned.m16n8k8.row.col.f32.tf32.tf32.f32 "
        "{%0,%1,%2,%3}, {%4,%5,%6,%7}, {%8,%9}, {%0,%1,%2,%3};"
        : "+f"(c[0]), "+f"(c[1]), "+f"(c[2]), "+f"(c[3])
        : "r"(a[0]), "r"(a[1]), "r"(a[2]), "r"(a[3]), "r"(b0), "r"(b1));
}
__device__ __forceinline__ void cp16(uint32_t s, const void* g) {
    asm volatile("cp.async.cg.shared.global [%0], [%1], 16;" :: "r"(s), "l"(g) : "memory");
}
#define CP_COMMIT() asm volatile("cp.async.commit_group;" ::: "memory")
#define CP_WAIT2()  asm volatile("cp.async.wait_group 2;" ::: "memory")

// ---------------- 0. weight convert (fp32 -> tf32-rounded fp32) ----------------
__global__ __launch_bounds__(256) void cvt_kernel(const float4* __restrict__ src,
                                                  float4* __restrict__ dst, int n4) {
    int i = blockIdx.x * blockDim.x + threadIdx.x;
    if (i < n4) {
        float4 v = src[i];
        v.x = tf32f(v.x); v.y = tf32f(v.y); v.z = tf32f(v.z); v.w = tf32f(v.w);
        dst[i] = v;
    }
}

// ---------------- 1. router ----------------
__global__ __launch_bounds__(256) void router_kernel(const float* __restrict__ x,
                                                     const float* __restrict__ gw) {
    int warp = (blockIdx.x * blockDim.x + threadIdx.x) >> 5;
    int lane = threadIdx.x & 31;
    if (warp >= N_TOK) return;
    const float* xr = x + (size_t)warp * DM;
    float acc[NE];
#pragma unroll
    for (int e = 0; e < NE; e++) acc[e] = 0.f;
    for (int i = lane; i < DM; i += 32) {
        float xv = xr[i];
#pragma unroll
        for (int e = 0; e < NE; e++) acc[e] += xv * gw[e * DM + i];
    }
#pragma unroll
    for (int off = 16; off > 0; off >>= 1)
#pragma unroll
        for (int e = 0; e < NE; e++) acc[e] += __shfl_xor_sync(0xffffffffu, acc[e], off);
    if (lane == 0) {
        float mx = acc[0];
#pragma unroll
        for (int e = 1; e < NE; e++) mx = fmaxf(mx, acc[e]);
        float p[NE], s = 0.f;
#pragma unroll
        for (int e = 0; e < NE; e++) { p[e] = expf(acc[e] - mx); s += p[e]; }
        float inv = 1.f / s;
        int i0 = 0;
#pragma unroll
        for (int e = 1; e < NE; e++) if (p[e] > p[i0]) i0 = e;
        int i1 = (i0 == 0) ? 1 : 0;
#pragma unroll
        for (int e = 0; e < NE; e++) if (e != i0 && e != i1 && p[e] > p[i1]) i1 = e;
#pragma unroll
        for (int e = 0; e < NE; e++) g_probs[warp * NE + e] = p[e] * inv;
        float p0 = p[i0] * inv, p1 = p[i1] * inv;
        float ws = p0 + p1 + 1e-10f;
        g_top_idx[warp * 2 + 0] = i0;  g_top_w[warp * 2 + 0] = p0 / ws;
        g_top_idx[warp * 2 + 1] = i1;  g_top_w[warp * 2 + 1] = p1 / ws;
    }
}

// ---------------- 2. capacity scan ----------------
__global__ __launch_bounds__(256) void scan_kernel() {
    int k = blockIdx.x;
    int t = threadIdx.x;
    const int CH = N_TOK / 256;
    __shared__ int cnt[256][NE];
    int local[NE];
#pragma unroll
    for (int e = 0; e < NE; e++) local[e] = 0;
    for (int i = 0; i < CH; i++) local[g_top_idx[(t * CH + i) * 2 + k]]++;
#pragma unroll
    for (int e = 0; e < NE; e++) cnt[t][e] = local[e];
    __syncthreads();
    if (t < NE) {
        int run = 0;
        for (int i = 0; i < 256; i++) { int v = cnt[i][t]; cnt[i][t] = run; run += v; }
        g_cnt[k * NE + t] = run;
    }
    __syncthreads();
    int off[NE];
#pragma unroll
    for (int e = 0; e < NE; e++) off[e] = cnt[t][e];
    for (int i = 0; i < CH; i++) {
        int tk = (t * CH + i) * 2 + k;
        g_pos[tk] = off[g_top_idx[tk]]++;
    }
}

// ---------------- 3. gather (with tf32 rounding) ----------------
__global__ __launch_bounds__(256) void gather_kernel(const float* __restrict__ x) {
    int tk = blockIdx.x;
    int pos = g_pos[tk];
    if (pos >= CAP) return;
    int e = g_top_idx[tk];
    int k = tk & 1, t = tk >> 1;
    float4*       dst = (float4*)(g_buf + ((size_t)(k * NE + e) * CAP + pos) * DM);
    const float4* src = (const float4*)(x + (size_t)t * DM);
    float4 v = src[threadIdx.x];
    v.x = tf32f(v.x); v.y = tf32f(v.y); v.z = tf32f(v.z); v.w = tf32f(v.w);
    dst[threadIdx.x] = v;
}

// ---------------- 4. gemm13: block 128M x 128N(x2 mats), warp 64x32(x2), 3-stage cp.async ----------------
__global__ __launch_bounds__(256) void gemm13_mma(int dummy) {
    int z = blockIdx.z, e = z & (NE - 1);
    int rows = g_cnt[z]; if (rows > CAP) rows = CAP;
    int m0 = blockIdx.y * 128; if (m0 >= rows) return;
    int n0 = blockIdx.x * 128;

    extern __shared__ char dsm[];
    uint32_t sb = smem_u32(dsm);

    const float* gA  = g_buf  + (size_t)z * CAP * DM + (size_t)m0 * DM;
    const float* gB1 = g_w1t + (size_t)e * DFF * DM + (size_t)n0 * DM;
    const float* gB3 = g_w3t + (size_t)e * DFF * DM + (size_t)n0 * DM;

    int tid = threadIdx.x, wid = tid >> 5, lane = tid & 31;
    int wm = wid >> 2, wn = wid & 3;             // 2M x 4N warps
    int g = lane >> 2, tg = lane & 3;

    auto issue = [&](int c, int s) {
        uint32_t st = sb + (uint32_t)s * SSTAGE;
        int k0 = c * 32;
#pragma unroll
        for (int i = 0; i < 4; i++) {
            int f = tid + i * 256, r = f >> 3, c4 = f & 7;
            cp16(st + r * SROWB + c4 * 16, gA + (size_t)r * DM + k0 + c4 * 4);
        }
#pragma unroll
        for (int i = 0; i < 4; i++) {
            int f = tid + i * 256, r = f >> 3, c4 = f & 7;
            cp16(st + 18432u + r * SROWB + c4 * 16, gB1 + (size_t)r * DM + k0 + c4 * 4);
        }
#pragma unroll
        for (int i = 0; i < 4; i++) {
            int f = tid + i * 256, r = f >> 3, c4 = f & 7;
            cp16(st + 36864u + r * SROWB + c4 * 16, gB3 + (size_t)r * DM + k0 + c4 * 4);
        }
    };

    float acc1[4][4][4], acc2[4][4][4];
#pragma unroll
    for (int mi = 0; mi < 4; mi++)
#pragma unroll
        for (int ni = 0; ni < 4; ni++)
#pragma unroll
            for (int r = 0; r < 4; r++) { acc1[mi][ni][r] = 0.f; acc2[mi][ni][r] = 0.f; }

    const int NC = DM / 32;   // 32
    issue(0, 0); CP_COMMIT();
    issue(1, 1); CP_COMMIT();

    for (int c = 0; c < NC; c++) {
        if (c + 2 < NC) issue(c + 2, (c + 2) % 3);
        CP_COMMIT();
        CP_WAIT2();
        __syncthreads();
        const float* As  = (const float*)(dsm + (c % 3) * SSTAGE);
        const float* B1s = As + 18432 / 4;
        const float* B3s = As + 36864 / 4;
#pragma unroll
        for (int kk = 0; kk < 4; kk++) {
            int k = kk * 8;
            uint32_t a[4][4];
#pragma unroll
            for (int mi = 0; mi < 4; mi++) {
                int mb = wm * 64 + mi * 16;
                a[mi][0] = __float_as_uint(As[(mb + g) * PAD + k + tg]);
                a[mi][1] = __float_as_uint(As[(mb + 8 + g) * PAD + k + tg]);
                a[mi][2] = __float_as_uint(As[(mb + g) * PAD + k + 4 + tg]);
                a[mi][3] = __float_as_uint(As[(mb + 8 + g) * PAD + k + 4 + tg]);
            }
#pragma unroll
            for (int ni = 0; ni < 4; ni++) {
                int nb = wn * 32 + ni * 8;
                uint32_t b0 = __float_as_uint(B1s[(nb + g) * PAD + k + tg]);
                uint32_t b1 = __float_as_uint(B1s[(nb + g) * PAD + k + 4 + tg]);
#pragma unroll
                for (int mi = 0; mi < 4; mi++) mma_tf32(acc1[mi][ni], a[mi], b0, b1);
                uint32_t d0 = __float_as_uint(B3s[(nb + g) * PAD + k + tg]);
                uint32_t d1 = __float_as_uint(B3s[(nb + g) * PAD + k + 4 + tg]);
#pragma unroll
                for (int mi = 0; mi < 4; mi++) mma_tf32(acc2[mi][ni], a[mi], d0, d1);
            }
        }
        __syncthreads();
    }

    float* H = g_h + (size_t)z * CAP * DFF;
#pragma unroll
    for (int mi = 0; mi < 4; mi++)
#pragma unroll
        for (int half = 0; half < 2; half++) {
            int m = m0 + wm * 64 + mi * 16 + half * 8 + g;
            if (m < rows) {
#pragma unroll
                for (int ni = 0; ni < 4; ni++) {
                    float v0 = acc1[mi][ni][half * 2 + 0];
                    float v1 = acc1[mi][ni][half * 2 + 1];
                    float o0 = tf32f((v0 / (1.f + expf(-v0))) * acc2[mi][ni][half * 2 + 0]);
                    float o1 = tf32f((v1 / (1.f + expf(-v1))) * acc2[mi][ni][half * 2 + 1]);
                    int col = n0 + wn * 32 + ni * 8 + 2 * tg;
                    *(float2*)&H[(size_t)m * DFF + col] = make_float2(o0, o1);
                }
            }
        }
}

// ---------------- 5. gemm2: block 128M x 256N, warp 64x64, 3-stage cp.async ----------------
__global__ __launch_bounds__(256) void gemm2_mma(int dummy) {
    int z = blockIdx.z, e = z & (NE - 1);
    int rows = g_cnt[z]; if (rows > CAP) rows = CAP;
    int m0 = blockIdx.y * 128; if (m0 >= rows) return;
    int n0 = blockIdx.x * 256;

    extern __shared__ char dsm[];
    uint32_t sb = smem_u32(dsm);

    const float* gA = g_h   + (size_t)z * CAP * DFF + (size_t)m0 * DFF;
    const float* gB = g_w2t + (size_t)e * DM * DFF + (size_t)n0 * DFF;

    int tid = threadIdx.x, wid = tid >> 5, lane = tid & 31;
    int wm = wid >> 2, wn = wid & 3;
    int g = lane >> 2, tg = lane & 3;

    auto issue = [&](int c, int s) {
        uint32_t st = sb + (uint32_t)s * SSTAGE;
        int k0 = c * 32;
#pragma unroll
        for (int i = 0; i < 4; i++) {
            int f = tid + i * 256, r = f >> 3, c4 = f & 7;
            cp16(st + r * SROWB + c4 * 16, gA + (size_t)r * DFF + k0 + c4 * 4);
        }
#pragma unroll
        for (int i = 0; i < 8; i++) {
            int f = tid + i * 256, r = f >> 3, c4 = f & 7;
            cp16(st + 18432u + r * SROWB + c4 * 16, gB + (size_t)r * DFF + k0 + c4 * 4);
        }
    };

    float acc[4][8][4];
#pragma unroll
    for (int mi = 0; mi < 4; mi++)
#pragma unroll
        for (int ni = 0; ni < 8; ni++)
#pragma unroll
            for (int r = 0; r < 4; r++) acc[mi][ni][r] = 0.f;

    const int NC = DFF / 32;  // 128
    issue(0, 0); CP_COMMIT();
    issue(1, 1); CP_COMMIT();

    for (int c = 0; c < NC; c++) {
        if (c + 2 < NC) issue(c + 2, (c + 2) % 3);
        CP_COMMIT();
        CP_WAIT2();
        __syncthreads();
        const float* As = (const float*)(dsm + (c % 3) * SSTAGE);
        const float* Bs = As + 18432 / 4;
#pragma unroll
        for (int kk = 0; kk < 4; kk++) {
            int k = kk * 8;
            uint32_t a[4][4];
#pragma unroll
            for (int mi = 0; mi < 4; mi++) {
                int mb = wm * 64 + mi * 16;
                a[mi][0] = __float_as_uint(As[(mb + g) * PAD + k + tg]);
                a[mi][1] = __float_as_uint(As[(mb + 8 + g) * PAD + k + tg]);
                a[mi][2] = __float_as_uint(As[(mb + g) * PAD + k + 4 + tg]);
                a[mi][3] = __float_as_uint(As[(mb + 8 + g) * PAD + k + 4 + tg]);
            }
#pragma unroll
            for (int ni = 0; ni < 8; ni++) {
                int nb = wn * 64 + ni * 8;
                uint32_t b0 = __float_as_uint(Bs[(nb + g) * PAD + k + tg]);
                uint32_t b1 = __float_as_uint(Bs[(nb + g) * PAD + k + 4 + tg]);
#pragma unroll
                for (int mi = 0; mi < 4; mi++) mma_tf32(acc[mi][ni], a[mi], b0, b1);
            }
        }
        __syncthreads();
    }

    float* O = g_ob + (size_t)z * CAP * DM;
#pragma unroll
    for (int mi = 0; mi < 4; mi++)
#pragma unroll
        for (int half = 0; half < 2; half++) {
            int m = m0 + wm * 64 + mi * 16 + half * 8 + g;
            if (m < rows) {
#pragma unroll
                for (int ni = 0; ni < 8; ni++) {
                    int col = n0 + wn * 64 + ni * 8 + 2 * tg;
                    *(float2*)&O[(size_t)m * DM + col] =
                        make_float2(acc[mi][ni][half * 2 + 0], acc[mi][ni][half * 2 + 1]);
                }
            }
        }
}

// ---------------- 6. weighted scatter/combine ----------------
__global__ __launch_bounds__(256) void scatter_kernel(float* __restrict__ out) {
    int t = blockIdx.x;
    int d4 = threadIdx.x;
    float4 acc = {0.f, 0.f, 0.f, 0.f};
#pragma unroll
    for (int k = 0; k < TOPK; k++) {
        int tk = t * 2 + k;
        int pos = g_pos[tk];
        if (pos < CAP) {
            int e = g_top_idx[tk];
            float w = g_top_w[tk];
            float4 v = ((const float4*)(g_ob + ((size_t)(k * NE + e) * CAP + pos) * DM))[d4];
            acc.x += v.x * w; acc.y += v.y * w; acc.z += v.z * w; acc.w += v.w * w;
        }
    }
    ((float4*)(out + (size_t)t * DM))[d4] = acc;
}

// ---------------- 7. aux loss ----------------
__global__ __launch_bounds__(256) void aux_kernel(float* __restrict__ out, int out_size) {
    __shared__ float red[256];
    __shared__ float Ps[NE];
    int tid = threadIdx.x;
    float loc[NE];
#pragma unroll
    for (int e = 0; e < NE; e++) loc[e] = 0.f;
    for (int i = tid; i < N_TOK; i += 256) {
#pragma unroll
        for (int e = 0; e < NE; e++) loc[e] += g_probs[i * NE + e];
    }
    for (int e = 0; e < NE; e++) {
        red[tid] = loc[e];
        __syncthreads();
        for (int s = 128; s > 0; s >>= 1) {
            if (tid < s) red[tid] += red[tid + s];
            __syncthreads();
        }
        if (tid == 0) Ps[e] = red[0];
        __syncthreads();
    }
    if (tid == 0) {
        float aux = 0.f;
        for (int e = 0; e < NE; e++) {
            float f = (float)(g_cnt[e] + g_cnt[NE + e]) / (float)(N_TOK * TOPK);
            float P = Ps[e] / (float)N_TOK;
            aux += f * P;
        }
        out[out_size - 1] = aux * (float)NE;
    }
}

// ---------------- launch ----------------
extern "C" void kernel_launch(void* const* d_in, const int* in_sizes, int n_in,
                              void* d_out, int out_size) {
    const float* x  = (const float*)d_in[0];
    const float* gw = (const float*)d_in[1];
    const float* w1 = (const float*)d_in[2];
    const float* w2 = (const float*)d_in[3];
    const float* w3 = (const float*)d_in[4];
    float* out = (float*)d_out;

    const int SMEM = 3 * SSTAGE;   // 165888
    static int configured = 0;
    cudaFuncSetAttribute(gemm13_mma, cudaFuncAttributeMaxDynamicSharedMemorySize, SMEM);
    cudaFuncSetAttribute(gemm2_mma,  cudaFuncAttributeMaxDynamicSharedMemorySize, SMEM);
    (void)configured;

    float* w1t; cudaGetSymbolAddress((void**)&w1t, g_w1t);
    float* w3t; cudaGetSymbolAddress((void**)&w3t, g_w3t);
    float* w2t; cudaGetSymbolAddress((void**)&w2t, g_w2t);

    const int N4 = NE * DFF * DM / 4;   // 8388608
    cvt_kernel<<<(N4 + 255) / 256, 256>>>((const float4*)w1, (float4*)w1t, N4);
    cvt_kernel<<<(N4 + 255) / 256, 256>>>((const float4*)w3, (float4*)w3t, N4);
    cvt_kernel<<<(N4 + 255) / 256, 256>>>((const float4*)w2, (float4*)w2t, N4);

    router_kernel<<<N_TOK / 8, 256>>>(x, gw);
    scan_kernel<<<2, 256>>>();
    gather_kernel<<<N_TOK * TOPK, 256>>>(x);

    dim3 g1(DFF / 128, CAP / 128, TOPK * NE);   // 32 x 10 x 16
    gemm13_mma<<<g1, 256, SMEM>>>(0);

    dim3 g2(DM / 256, CAP / 128, TOPK * NE);    // 4 x 10 x 16
    gemm2_mma<<<g2, 256, SMEM>>>(0);

    scatter_kernel<<<N_TOK, 256>>>(out);
    aux_kernel<<<1, 256>>>(out, out_size);
}

// round 5
// speedup vs baseline: 5.9437x; 1.0091x over previous
#include <cuda_runtime.h>
#include <math.h>
#include <stdint.h>

#define N_TOK 8192
#define DM    1024
#define DFF   4096
#define NE    8
#define TOPK  2
#define CAP   1280
#define PAD   36          // smem row stride in floats
#define SROWB 144         // row stride bytes
#define SSTAGE 55296      // bytes per pipeline stage (384 rows x 144B)

// ---------------- scratch ----------------
__device__ float g_buf[2 * NE * CAP * DM];
__device__ float g_h  [2 * NE * CAP * DFF];
__device__ float g_ob [2 * NE * CAP * DM];
__device__ float g_w1t[NE * DFF * DM];
__device__ float g_w3t[NE * DFF * DM];
__device__ float g_w2t[NE * DM * DFF];
__device__ float g_probs[N_TOK * NE];
__device__ int   g_top_idx[N_TOK * TOPK];
__device__ float g_top_w [N_TOK * TOPK];
__device__ int   g_pos   [N_TOK * TOPK];
__device__ int   g_cnt   [TOPK * NE];

// ---------------- helpers ----------------
__device__ __forceinline__ uint32_t smem_u32(const void* p) {
    uint32_t a;
    asm("{ .reg .u64 t; cvta.to.shared.u64 t, %1; cvt.u32.u64 %0, t; }" : "=r"(a) : "l"(p));
    return a;
}
__device__ __forceinline__ float tf32f(float x) {
    uint32_t r; asm("cvt.rna.tf32.f32 %0, %1;" : "=r"(r) : "f"(x));
    return __uint_as_float(r);
}
__device__ __forceinline__ void mma_tf32(float* c, const uint32_t* a, uint32_t b0, uint32_t b1) {
    asm volatile(
        "mma.sync.aligned.m16n8k8.row.col.f32.tf32.tf32.f32 "
        "{%0,%1,%2,%3}, {%4,%5,%6,%7}, {%8,%9}, {%0,%1,%2,%3};"
        : "+f"(c[0]), "+f"(c[1]), "+f"(c[2]), "+f"(c[3])
        : "r"(a[0]), "r"(a[1]), "r"(a[2]), "r"(a[3]), "r"(b0), "r"(b1));
}
__device__ __forceinline__ void cp16(uint32_t s, const void* g) {
    asm volatile("cp.async.cg.shared.global [%0], [%1], 16;" :: "r"(s), "l"(g) : "memory");
}
#define CP_COMMIT() asm volatile("cp.async.commit_group;" ::: "memory")
#define CP_WAIT1()  asm volatile("cp.async.wait_group 1;" ::: "memory")

// ---------------- 0. weight convert (fp32 -> tf32-rounded fp32) ----------------
__global__ __launch_bounds__(256) void cvt_kernel(const float4* __restrict__ src,
                                                  float4* __restrict__ dst, int n4) {
    int i = blockIdx.x * blockDim.x + threadIdx.x;
    if (i < n4) {
        float4 v = src[i];
        v.x = tf32f(v.x); v.y = tf32f(v.y); v.z = tf32f(v.z); v.w = tf32f(v.w);
        dst[i] = v;
    }
}

// ---------------- 1. router ----------------
__global__ __launch_bounds__(256) void router_kernel(const float* __restrict__ x,
                                                     const float* __restrict__ gw) {
    int warp = (blockIdx.x * blockDim.x + threadIdx.x) >> 5;
    int lane = threadIdx.x & 31;
    if (warp >= N_TOK) return;
    const float* xr = x + (size_t)warp * DM;
    float acc[NE];
#pragma unroll
    for (int e = 0; e < NE; e++) acc[e] = 0.f;
    for (int i = lane; i < DM; i += 32) {
        float xv = xr[i];
#pragma unroll
        for (int e = 0; e < NE; e++) acc[e] += xv * gw[e * DM + i];
    }
#pragma unroll
    for (int off = 16; off > 0; off >>= 1)
#pragma unroll
        for (int e = 0; e < NE; e++) acc[e] += __shfl_xor_sync(0xffffffffu, acc[e], off);
    if (lane == 0) {
        float mx = acc[0];
#pragma unroll
        for (int e = 1; e < NE; e++) mx = fmaxf(mx, acc[e]);
        float p[NE], s = 0.f;
#pragma unroll
        for (int e = 0; e < NE; e++) { p[e] = expf(acc[e] - mx); s += p[e]; }
        float inv = 1.f / s;
        int i0 = 0;
#pragma unroll
        for (int e = 1; e < NE; e++) if (p[e] > p[i0]) i0 = e;
        int i1 = (i0 == 0) ? 1 : 0;
#pragma unroll
        for (int e = 0; e < NE; e++) if (e != i0 && e != i1 && p[e] > p[i1]) i1 = e;
#pragma unroll
        for (int e = 0; e < NE; e++) g_probs[warp * NE + e] = p[e] * inv;
        float p0 = p[i0] * inv, p1 = p[i1] * inv;
        float ws = p0 + p1 + 1e-10f;
        g_top_idx[warp * 2 + 0] = i0;  g_top_w[warp * 2 + 0] = p0 / ws;
        g_top_idx[warp * 2 + 1] = i1;  g_top_w[warp * 2 + 1] = p1 / ws;
    }
}

// ---------------- 2. capacity scan ----------------
__global__ __launch_bounds__(256) void scan_kernel() {
    int k = blockIdx.x;
    int t = threadIdx.x;
    const int CH = N_TOK / 256;
    __shared__ int cnt[256][NE];
    int local[NE];
#pragma unroll
    for (int e = 0; e < NE; e++) local[e] = 0;
    for (int i = 0; i < CH; i++) local[g_top_idx[(t * CH + i) * 2 + k]]++;
#pragma unroll
    for (int e = 0; e < NE; e++) cnt[t][e] = local[e];
    __syncthreads();
    if (t < NE) {
        int run = 0;
        for (int i = 0; i < 256; i++) { int v = cnt[i][t]; cnt[i][t] = run; run += v; }
        g_cnt[k * NE + t] = run;
    }
    __syncthreads();
    int off[NE];
#pragma unroll
    for (int e = 0; e < NE; e++) off[e] = cnt[t][e];
    for (int i = 0; i < CH; i++) {
        int tk = (t * CH + i) * 2 + k;
        g_pos[tk] = off[g_top_idx[tk]]++;
    }
}

// ---------------- 3. gather (with tf32 rounding) ----------------
__global__ __launch_bounds__(256) void gather_kernel(const float* __restrict__ x) {
    int tk = blockIdx.x;
    int pos = g_pos[tk];
    if (pos >= CAP) return;
    int e = g_top_idx[tk];
    int k = tk & 1, t = tk >> 1;
    float4*       dst = (float4*)(g_buf + ((size_t)(k * NE + e) * CAP + pos) * DM);
    const float4* src = (const float4*)(x + (size_t)t * DM);
    float4 v = src[threadIdx.x];
    v.x = tf32f(v.x); v.y = tf32f(v.y); v.z = tf32f(v.z); v.w = tf32f(v.w);
    dst[threadIdx.x] = v;
}

// ---------------- 4. gemm13: 128M x 128N(x2 mats), warp 64x32(x2), 3-stage + frag double-buffer ----------------
__global__ __launch_bounds__(256) void gemm13_mma(int dummy) {
    int z = blockIdx.z, e = z & (NE - 1);
    int rows = g_cnt[z]; if (rows > CAP) rows = CAP;
    int m0 = blockIdx.y * 128; if (m0 >= rows) return;
    int n0 = blockIdx.x * 128;

    extern __shared__ char dsm[];
    uint32_t sb = smem_u32(dsm);

    const float* gA  = g_buf + (size_t)z * CAP * DM + (size_t)m0 * DM;
    const float* gB1 = g_w1t + (size_t)e * DFF * DM + (size_t)n0 * DM;
    const float* gB3 = g_w3t + (size_t)e * DFF * DM + (size_t)n0 * DM;

    int tid = threadIdx.x, wid = tid >> 5, lane = tid & 31;
    int wm = wid >> 2, wn = wid & 3;
    int g = lane >> 2, tg = lane & 3;

    auto issue = [&](int c, int s) {
        uint32_t st = sb + (uint32_t)s * SSTAGE;
        int k0 = c * 32;
#pragma unroll
        for (int i = 0; i < 4; i++) {
            int f = tid + i * 256, r = f >> 3, c4 = f & 7;
            cp16(st + r * SROWB + c4 * 16, gA + (size_t)r * DM + k0 + c4 * 4);
        }
#pragma unroll
        for (int i = 0; i < 4; i++) {
            int f = tid + i * 256, r = f >> 3, c4 = f & 7;
            cp16(st + 18432u + r * SROWB + c4 * 16, gB1 + (size_t)r * DM + k0 + c4 * 4);
        }
#pragma unroll
        for (int i = 0; i < 4; i++) {
            int f = tid + i * 256, r = f >> 3, c4 = f & 7;
            cp16(st + 36864u + r * SROWB + c4 * 16, gB3 + (size_t)r * DM + k0 + c4 * 4);
        }
    };

    float acc1[4][4][4], acc2[4][4][4];
#pragma unroll
    for (int mi = 0; mi < 4; mi++)
#pragma unroll
        for (int ni = 0; ni < 4; ni++)
#pragma unroll
            for (int r = 0; r < 4; r++) { acc1[mi][ni][r] = 0.f; acc2[mi][ni][r] = 0.f; }

    uint32_t af[2][4][4], b1f[2][4][2], b3f[2][4][2];

    auto loadfrag = [&](const float* As, const float* B1s, const float* B3s, int kk, int buf) {
        int k = kk * 8;
#pragma unroll
        for (int mi = 0; mi < 4; mi++) {
            int mb = wm * 64 + mi * 16;
            af[buf][mi][0] = __float_as_uint(As[(mb + g) * PAD + k + tg]);
            af[buf][mi][1] = __float_as_uint(As[(mb + 8 + g) * PAD + k + tg]);
            af[buf][mi][2] = __float_as_uint(As[(mb + g) * PAD + k + 4 + tg]);
            af[buf][mi][3] = __float_as_uint(As[(mb + 8 + g) * PAD + k + 4 + tg]);
        }
#pragma unroll
        for (int ni = 0; ni < 4; ni++) {
            int nb = wn * 32 + ni * 8;
            b1f[buf][ni][0] = __float_as_uint(B1s[(nb + g) * PAD + k + tg]);
            b1f[buf][ni][1] = __float_as_uint(B1s[(nb + g) * PAD + k + 4 + tg]);
            b3f[buf][ni][0] = __float_as_uint(B3s[(nb + g) * PAD + k + tg]);
            b3f[buf][ni][1] = __float_as_uint(B3s[(nb + g) * PAD + k + 4 + tg]);
        }
    };

    const int NC = DM / 32;   // 32
    issue(0, 0); CP_COMMIT();
    issue(1, 1); CP_COMMIT();

    for (int c = 0; c < NC; c++) {
        CP_WAIT1();
        __syncthreads();
        if (c + 2 < NC) issue(c + 2, (c + 2) % 3);
        CP_COMMIT();
        const float* As  = (const float*)(dsm + (c % 3) * SSTAGE);
        const float* B1s = As + 18432 / 4;
        const float* B3s = As + 36864 / 4;
        loadfrag(As, B1s, B3s, 0, 0);
#pragma unroll
        for (int kk = 0; kk < 4; kk++) {
            int cur = kk & 1;
            if (kk < 3) loadfrag(As, B1s, B3s, kk + 1, cur ^ 1);
#pragma unroll
            for (int ni = 0; ni < 4; ni++) {
#pragma unroll
                for (int mi = 0; mi < 4; mi++)
                    mma_tf32(acc1[mi][ni], af[cur][mi], b1f[cur][ni][0], b1f[cur][ni][1]);
#pragma unroll
                for (int mi = 0; mi < 4; mi++)
                    mma_tf32(acc2[mi][ni], af[cur][mi], b3f[cur][ni][0], b3f[cur][ni][1]);
            }
        }
        __syncthreads();
    }

    float* H = g_h + (size_t)z * CAP * DFF;
#pragma unroll
    for (int mi = 0; mi < 4; mi++)
#pragma unroll
        for (int half = 0; half < 2; half++) {
            int m = m0 + wm * 64 + mi * 16 + half * 8 + g;
            if (m < rows) {
#pragma unroll
                for (int ni = 0; ni < 4; ni++) {
                    float v0 = acc1[mi][ni][half * 2 + 0];
                    float v1 = acc1[mi][ni][half * 2 + 1];
                    float o0 = tf32f((v0 / (1.f + expf(-v0))) * acc2[mi][ni][half * 2 + 0]);
                    float o1 = tf32f((v1 / (1.f + expf(-v1))) * acc2[mi][ni][half * 2 + 1]);
                    int col = n0 + wn * 32 + ni * 8 + 2 * tg;
                    *(float2*)&H[(size_t)m * DFF + col] = make_float2(o0, o1);
                }
            }
        }
}

// ---------------- 5. gemm2: 128M x 256N, warp 64x64, 3-stage + frag double-buffer ----------------
__global__ __launch_bounds__(256) void gemm2_mma(int dummy) {
    int z = blockIdx.z, e = z & (NE - 1);
    int rows = g_cnt[z]; if (rows > CAP) rows = CAP;
    int m0 = blockIdx.y * 128; if (m0 >= rows) return;
    int n0 = blockIdx.x * 256;

    extern __shared__ char dsm[];
    uint32_t sb = smem_u32(dsm);

    const float* gA = g_h   + (size_t)z * CAP * DFF + (size_t)m0 * DFF;
    const float* gB = g_w2t + (size_t)e * DM * DFF + (size_t)n0 * DFF;

    int tid = threadIdx.x, wid = tid >> 5, lane = tid & 31;
    int wm = wid >> 2, wn = wid & 3;
    int g = lane >> 2, tg = lane & 3;

    auto issue = [&](int c, int s) {
        uint32_t st = sb + (uint32_t)s * SSTAGE;
        int k0 = c * 32;
#pragma unroll
        for (int i = 0; i < 4; i++) {
            int f = tid + i * 256, r = f >> 3, c4 = f & 7;
            cp16(st + r * SROWB + c4 * 16, gA + (size_t)r * DFF + k0 + c4 * 4);
        }
#pragma unroll
        for (int i = 0; i < 8; i++) {
            int f = tid + i * 256, r = f >> 3, c4 = f & 7;
            cp16(st + 18432u + r * SROWB + c4 * 16, gB + (size_t)r * DFF + k0 + c4 * 4);
        }
    };

    float acc[4][8][4];
#pragma unroll
    for (int mi = 0; mi < 4; mi++)
#pragma unroll
        for (int ni = 0; ni < 8; ni++)
#pragma unroll
            for (int r = 0; r < 4; r++) acc[mi][ni][r] = 0.f;

    uint32_t af[2][4][4], bf[2][8][2];

    auto loadfrag = [&](const float* As, const float* Bs, int kk, int buf) {
        int k = kk * 8;
#pragma unroll
        for (int mi = 0; mi < 4; mi++) {
            int mb = wm * 64 + mi * 16;
            af[buf][mi][0] = __float_as_uint(As[(mb + g) * PAD + k + tg]);
            af[buf][mi][1] = __float_as_uint(As[(mb + 8 + g) * PAD + k + tg]);
            af[buf][mi][2] = __float_as_uint(As[(mb + g) * PAD + k + 4 + tg]);
            af[buf][mi][3] = __float_as_uint(As[(mb + 8 + g) * PAD + k + 4 + tg]);
        }
#pragma unroll
        for (int ni = 0; ni < 8; ni++) {
            int nb = wn * 64 + ni * 8;
            bf[buf][ni][0] = __float_as_uint(Bs[(nb + g) * PAD + k + tg]);
            bf[buf][ni][1] = __float_as_uint(Bs[(nb + g) * PAD + k + 4 + tg]);
        }
    };

    const int NC = DFF / 32;  // 128
    issue(0, 0); CP_COMMIT();
    issue(1, 1); CP_COMMIT();

    for (int c = 0; c < NC; c++) {
        CP_WAIT1();
        __syncthreads();
        if (c + 2 < NC) issue(c + 2, (c + 2) % 3);
        CP_COMMIT();
        const float* As = (const float*)(dsm + (c % 3) * SSTAGE);
        const float* Bs = As + 18432 / 4;
        loadfrag(As, Bs, 0, 0);
#pragma unroll
        for (int kk = 0; kk < 4; kk++) {
            int cur = kk & 1;
            if (kk < 3) loadfrag(As, Bs, kk + 1, cur ^ 1);
#pragma unroll
            for (int ni = 0; ni < 8; ni++)
#pragma unroll
                for (int mi = 0; mi < 4; mi++)
                    mma_tf32(acc[mi][ni], af[cur][mi], bf[cur][ni][0], bf[cur][ni][1]);
        }
        __syncthreads();
    }

    float* O = g_ob + (size_t)z * CAP * DM;
#pragma unroll
    for (int mi = 0; mi < 4; mi++)
#pragma unroll
        for (int half = 0; half < 2; half++) {
            int m = m0 + wm * 64 + mi * 16 + half * 8 + g;
            if (m < rows) {
#pragma unroll
                for (int ni = 0; ni < 8; ni++) {
                    int col = n0 + wn * 64 + ni * 8 + 2 * tg;
                    *(float2*)&O[(size_t)m * DM + col] =
                        make_float2(acc[mi][ni][half * 2 + 0], acc[mi][ni][half * 2 + 1]);
                }
            }
        }
}

// ---------------- 6. weighted scatter/combine ----------------
__global__ __launch_bounds__(256) void scatter_kernel(float* __restrict__ out) {
    int t = blockIdx.x;
    int d4 = threadIdx.x;
    float4 acc = {0.f, 0.f, 0.f, 0.f};
#pragma unroll
    for (int k = 0; k < TOPK; k++) {
        int tk = t * 2 + k;
        int pos = g_pos[tk];
        if (pos < CAP) {
            int e = g_top_idx[tk];
            float w = g_top_w[tk];
            float4 v = ((const float4*)(g_ob + ((size_t)(k * NE + e) * CAP + pos) * DM))[d4];
            acc.x += v.x * w; acc.y += v.y * w; acc.z += v.z * w; acc.w += v.w * w;
        }
    }
    ((float4*)(out + (size_t)t * DM))[d4] = acc;
}

// ---------------- 7. aux loss ----------------
__global__ __launch_bounds__(256) void aux_kernel(float* __restrict__ out, int out_size) {
    __shared__ float red[256];
    __shared__ float Ps[NE];
    int tid = threadIdx.x;
    float loc[NE];
#pragma unroll
    for (int e = 0; e < NE; e++) loc[e] = 0.f;
    for (int i = tid; i < N_TOK; i += 256) {
#pragma unroll
        for (int e = 0; e < NE; e++) loc[e] += g_probs[i * NE + e];
    }
    for (int e = 0; e < NE; e++) {
        red[tid] = loc[e];
        __syncthreads();
        for (int s = 128; s > 0; s >>= 1) {
            if (tid < s) red[tid] += red[tid + s];
            __syncthreads();
        }
        if (tid == 0) Ps[e] = red[0];
        __syncthreads();
    }
    if (tid == 0) {
        float aux = 0.f;
        for (int e = 0; e < NE; e++) {
            float f = (float)(g_cnt[e] + g_cnt[NE + e]) / (float)(N_TOK * TOPK);
            float P = Ps[e] / (float)N_TOK;
            aux += f * P;
        }
        out[out_size - 1] = aux * (float)NE;
    }
}

// ---------------- launch ----------------
extern "C" void kernel_launch(void* const* d_in, const int* in_sizes, int n_in,
                              void* d_out, int out_size) {
    const float* x  = (const float*)d_in[0];
    const float* gw = (const float*)d_in[1];
    const float* w1 = (const float*)d_in[2];
    const float* w2 = (const float*)d_in[3];
    const float* w3 = (const float*)d_in[4];
    float* out = (float*)d_out;

    const int SMEM = 3 * SSTAGE;   // 165888
    cudaFuncSetAttribute(gemm13_mma, cudaFuncAttributeMaxDynamicSharedMemorySize, SMEM);
    cudaFuncSetAttribute(gemm2_mma,  cudaFuncAttributeMaxDynamicSharedMemorySize, SMEM);

    float* w1t; cudaGetSymbolAddress((void**)&w1t, g_w1t);
    float* w3t; cudaGetSymbolAddress((void**)&w3t, g_w3t);
    float* w2t; cudaGetSymbolAddress((void**)&w2t, g_w2t);

    const int N4 = NE * DFF * DM / 4;
    cvt_kernel<<<(N4 + 255) / 256, 256>>>((const float4*)w1, (float4*)w1t, N4);
    cvt_kernel<<<(N4 + 255) / 256, 256>>>((const float4*)w3, (float4*)w3t, N4);
    cvt_kernel<<<(N4 + 255) / 256, 256>>>((const float4*)w2, (float4*)w2t, N4);

    router_kernel<<<N_TOK / 8, 256>>>(x, gw);
    scan_kernel<<<2, 256>>>();
    gather_kernel<<<N_TOK * TOPK, 256>>>(x);

    dim3 g1(DFF / 128, CAP / 128, TOPK * NE);   // 32 x 10 x 16
    gemm13_mma<<<g1, 256, SMEM>>>(0);

    dim3 g2(DM / 256, CAP / 128, TOPK * NE);    // 4 x 10 x 16
    gemm2_mma<<<g2, 256, SMEM>>>(0);

    scatter_kernel<<<N_TOK, 256>>>(out);
    aux_kernel<<<1, 256>>>(out, out_size);
}